// round 14
// baseline (speedup 1.0000x reference)
#include <cuda_runtime.h>
#include <cuda_bf16.h>
#include <cstdint>

#define BQ 4
#define TQ 2048
#define DQ 1024
#define HQ 16
#define SQ 64
#define CQ 64
#define MROWS (BQ*TQ)   /* 8192 */
#define NCH (TQ/CQ)     /* 32 chunks */

typedef unsigned long long ULL;

// ---------------- device scratch ----------------------------------------------
__device__ __align__(256) __nv_bfloat16 g_wq[5u*1024u*1024u];
__device__ float         g_wscale[5];
__device__ float         g_partial[5*64];
__device__ unsigned      g_cnt[5];
__device__ __align__(256) __nv_bfloat16 g_xq[4u*MROWS*DQ];
__device__ float         g_xscale[4*MROWS];
__device__ __align__(256) float g_r[MROWS*DQ];
__device__ __align__(256) float g_k[MROWS*DQ];
__device__ __align__(256) float g_v[MROWS*DQ];
__device__ __align__(256) float g_gate[MROWS*DQ];
__device__ __align__(256) float g_y[MROWS*DQ];
__device__ __align__(256) __nv_bfloat16 g_xq5[MROWS*DQ];
__device__ float         g_xscale5[MROWS];
__device__ __align__(256) float g_state[64u*NCH*SQ*SQ];   // R_c then chunk-start states

// ---------------- PTX helpers --------------------------------------------------
__device__ __forceinline__ uint32_t smem_u32(const void* p) {
    uint32_t a;
    asm("{ .reg .u64 t; cvta.to.shared.u64 t, %1; cvt.u32.u64 %0, t; }" : "=r"(a) : "l"(p));
    return a;
}
__device__ __forceinline__ void cpasync16(uint32_t saddr, const void* g) {
    asm volatile("cp.async.cg.shared.global [%0], [%1], 16;" :: "r"(saddr), "l"(g) : "memory");
}
#define CP_COMMIT() asm volatile("cp.async.commit_group;" ::: "memory")

__device__ __forceinline__ void ldsm_x4(uint32_t& r0, uint32_t& r1, uint32_t& r2, uint32_t& r3,
                                        uint32_t addr) {
    asm volatile("ldmatrix.sync.aligned.m8n8.x4.shared.b16 {%0,%1,%2,%3}, [%4];"
        : "=r"(r0), "=r"(r1), "=r"(r2), "=r"(r3) : "r"(addr));
}
__device__ __forceinline__ void mma_bf16(float c[4], const uint32_t a[4], const uint32_t b[2]) {
    asm volatile(
        "mma.sync.aligned.m16n8k16.row.col.f32.bf16.bf16.f32 "
        "{%0,%1,%2,%3}, {%4,%5,%6,%7}, {%8,%9}, {%0,%1,%2,%3};\n"
        : "+f"(c[0]), "+f"(c[1]), "+f"(c[2]), "+f"(c[3])
        : "r"(a[0]), "r"(a[1]), "r"(a[2]), "r"(a[3]), "r"(b[0]), "r"(b[1]));
}

__device__ __forceinline__ ULL pk2(float a, float b) {
    ULL r; asm("mov.b64 %0, {%1, %2};" : "=l"(r) : "f"(a), "f"(b)); return r;
}
__device__ __forceinline__ void upk2(ULL v, float& a, float& b) {
    asm("mov.b64 {%0, %1}, %2;" : "=f"(a), "=f"(b) : "l"(v));
}
__device__ __forceinline__ ULL fma2(ULL a, ULL b, ULL c) {
    ULL d; asm("fma.rn.f32x2 %0, %1, %2, %3;" : "=l"(d) : "l"(a), "l"(b), "l"(c)); return d;
}
__device__ __forceinline__ ULL mul2(ULL a, ULL b) {
    ULL d; asm("mul.rn.f32x2 %0, %1, %2;" : "=l"(d) : "l"(a), "l"(b)); return d;
}

__device__ __forceinline__ float warpsum(float v) {
    #pragma unroll
    for (int o = 16; o; o >>= 1) v += __shfl_xor_sync(0xffffffffu, v, o);
    return v;
}
__device__ __forceinline__ uint32_t bf2bits(float a, float b) {
    __nv_bfloat162 h(__float2bfloat16(a), __float2bfloat16(b));
    return *(uint32_t*)&h;
}

// ---------------- weight scale (fused two-stage via atomic counter) -----------
__global__ void wq_scale_kernel(const float* __restrict__ w) {
    __shared__ float sh[8];
    __shared__ bool last;
    int z = blockIdx.y, blk = blockIdx.x, tid = threadIdx.x;
    const float* base = w + (size_t)z * 1048576u + (size_t)blk * 16384u;
    float s = 0.f;
    #pragma unroll
    for (int j = 0; j < 16; j++) {
        float4 v = *(const float4*)(base + (tid + j * 256) * 4);
        s += fabsf(v.x) + fabsf(v.y) + fabsf(v.z) + fabsf(v.w);
    }
    s = warpsum(s);
    if ((tid & 31) == 0) sh[tid >> 5] = s;
    __syncthreads();
    if (tid == 0) {
        float t = 0.f;
        #pragma unroll
        for (int i = 0; i < 8; i++) t += sh[i];
        g_partial[z * 64 + blk] = t;
        __threadfence();
        unsigned prev = atomicAdd(&g_cnt[z], 1u);
        last = (prev == 63u);
    }
    __syncthreads();
    if (last && tid < 32) {
        float t = g_partial[z * 64 + tid] + g_partial[z * 64 + 32 + tid];
        t = warpsum(t);
        if (tid == 0) {
            g_wscale[z] = fmaxf(t * (1.f / 1048576.f), 1e-8f);
            g_cnt[z] = 0u;
        }
    }
}

// ---------------- fused: weight quant (blocks 0..5119) + lnq4 (5120..7167) ----
__global__ void __launch_bounds__(256) quant_lnq4_kernel(
        const float* __restrict__ w, const float* __restrict__ x,
        const float* __restrict__ mu_r, const float* __restrict__ mu_k,
        const float* __restrict__ mu_v, const float* __restrict__ mu_g,
        const float* __restrict__ ln_g, const float* __restrict__ ln_b) {
    __shared__ float shst[4][2][2];
    __shared__ float shab[4][2];
    int tid = threadIdx.x;

    if (blockIdx.x < 5120) {
        int idx = (blockIdx.x * 256 + tid) * 4;
        int z = idx >> 20;
        float s = g_wscale[z];
        float4 wv = *(const float4*)(w + idx);
        float vv[4] = {wv.x, wv.y, wv.z, wv.w};
        __nv_bfloat16 q[4];
        #pragma unroll
        for (int j = 0; j < 4; j++) {
            float wn = vv[j] / s;
            wn = fminf(fmaxf(wn, -1.f), 1.f);
            q[j] = __float2bfloat16(rintf(wn));
        }
        *(__nv_bfloat162*)(g_wq + idx)     = __nv_bfloat162(q[0], q[1]);
        *(__nv_bfloat162*)(g_wq + idx + 2) = __nv_bfloat162(q[2], q[3]);
        return;
    }

    int blk = blockIdx.x - 5120;
    int rg = tid >> 6, lt = tid & 63, wip = (tid >> 5) & 1, lane = tid & 31;
    int m = blk * 4 + rg;
    int d0 = lt * 16;
    const float* xr = x + (size_t)m * DQ + d0;
    bool hp = (m & (TQ - 1)) != 0;
    const float* mus[4] = {mu_r, mu_k, mu_v, mu_g};

    float xv[16], dx[16];
    #pragma unroll
    for (int j = 0; j < 4; j++) {
        float4 a = *(const float4*)(xr + j * 4);
        float4 p = hp ? *(const float4*)(xr - DQ + j * 4) : make_float4(0.f, 0.f, 0.f, 0.f);
        xv[j*4+0] = a.x; xv[j*4+1] = a.y; xv[j*4+2] = a.z; xv[j*4+3] = a.w;
        dx[j*4+0] = p.x - a.x; dx[j*4+1] = p.y - a.y;
        dx[j*4+2] = p.z - a.z; dx[j*4+3] = p.w - a.w;
    }

    #pragma unroll 1
    for (int i = 0; i < 4; i++) {
        float inp[16];
        float s = 0.f, s2 = 0.f;
        const float* mup = mus[i] + d0;
        #pragma unroll
        for (int j = 0; j < 4; j++) {
            float4 mu = *(const float4*)(mup + j * 4);
            float v0 = fmaf(dx[j*4+0], mu.x, xv[j*4+0]);
            float v1 = fmaf(dx[j*4+1], mu.y, xv[j*4+1]);
            float v2 = fmaf(dx[j*4+2], mu.z, xv[j*4+2]);
            float v3 = fmaf(dx[j*4+3], mu.w, xv[j*4+3]);
            inp[j*4+0] = v0; inp[j*4+1] = v1; inp[j*4+2] = v2; inp[j*4+3] = v3;
            s += v0 + v1 + v2 + v3;
            s2 += v0*v0 + v1*v1 + v2*v2 + v3*v3;
        }
        s = warpsum(s); s2 = warpsum(s2);
        if (lane == 0) { shst[rg][wip][0] = s; shst[rg][wip][1] = s2; }
        __syncthreads();
        float ts  = shst[rg][0][0] + shst[rg][1][0];
        float ts2 = shst[rg][0][1] + shst[rg][1][1];
        float mean = ts * (1.f / DQ);
        float var = fmaxf(ts2 * (1.f / DQ) - mean * mean, 0.f);
        float rstd = rsqrtf(var + 1e-5f);
        const float* gp = ln_g + i * DQ + d0;
        const float* bp = ln_b + i * DQ + d0;
        float sa = 0.f;
        #pragma unroll
        for (int j = 0; j < 4; j++) {
            float4 gg = *(const float4*)(gp + j * 4);
            float4 bb = *(const float4*)(bp + j * 4);
            float v0 = (inp[j*4+0] - mean) * rstd * gg.x + bb.x;
            float v1 = (inp[j*4+1] - mean) * rstd * gg.y + bb.y;
            float v2 = (inp[j*4+2] - mean) * rstd * gg.z + bb.z;
            float v3 = (inp[j*4+3] - mean) * rstd * gg.w + bb.w;
            inp[j*4+0] = v0; inp[j*4+1] = v1; inp[j*4+2] = v2; inp[j*4+3] = v3;
            sa += fabsf(v0) + fabsf(v1) + fabsf(v2) + fabsf(v3);
        }
        sa = warpsum(sa);
        if (lane == 0) shab[rg][wip] = sa;
        __syncthreads();
        float ma = (shab[rg][0] + shab[rg][1]) * (1.f / DQ);
        float scale = fmaxf(ma, 1e-8f) * 2.5f / 127.f;
        float inv = 1.f / scale;
        size_t off = (size_t)i * MROWS * DQ + (size_t)m * DQ + d0;
        #pragma unroll
        for (int g = 0; g < 2; g++) {
            uint4 u;
            float q0 = rintf(fminf(fmaxf(inp[g*8+0] * inv, -127.f), 127.f));
            float q1 = rintf(fminf(fmaxf(inp[g*8+1] * inv, -127.f), 127.f));
            float q2 = rintf(fminf(fmaxf(inp[g*8+2] * inv, -127.f), 127.f));
            float q3 = rintf(fminf(fmaxf(inp[g*8+3] * inv, -127.f), 127.f));
            float q4 = rintf(fminf(fmaxf(inp[g*8+4] * inv, -127.f), 127.f));
            float q5 = rintf(fminf(fmaxf(inp[g*8+5] * inv, -127.f), 127.f));
            float q6 = rintf(fminf(fmaxf(inp[g*8+6] * inv, -127.f), 127.f));
            float q7 = rintf(fminf(fmaxf(inp[g*8+7] * inv, -127.f), 127.f));
            u.x = bf2bits(q0, q1); u.y = bf2bits(q2, q3);
            u.z = bf2bits(q4, q5); u.w = bf2bits(q6, q7);
            *(uint4*)(g_xq + off + g * 8) = u;
        }
        if (lt == 0) g_xscale[i * MROWS + m] = scale;
    }
}

// ---------------- mma.sync bf16 GEMM with ldmatrix + cp.async pipeline --------
#define GK_TILES 16
#define STAGE_BYTES 32768

__global__ void __launch_bounds__(256, 2) gemm_mma_kernel(float* __restrict__ out_final) {
    extern __shared__ char smem_raw[];
    uint32_t sb = (smem_u32(smem_raw) + 1023u) & ~1023u;
    int tid = threadIdx.x, warp = tid >> 5, lane = tid & 31;
    int wm = warp >> 2, wn = warp & 3;
    int gid = lane >> 2, tig = lane & 3;

    int proj = (gridDim.z > 1) ? blockIdx.z : 4;
    const __nv_bfloat16* Ag = (proj < 4) ? (g_xq + (size_t)proj * MROWS * DQ) : g_xq5;
    const __nv_bfloat16* Bg = g_wq + (size_t)proj * DQ * DQ;
    const __nv_bfloat16* Abase = Ag + (size_t)blockIdx.x * 128 * DQ;
    const __nv_bfloat16* Bbase = Bg + (size_t)blockIdx.y * 128 * DQ;

    int ldrow = tid >> 3, ldc = tid & 7;
    int rowA = wm * 64 + (lane & 7) + ((lane >> 3) & 1) * 8;
    uint32_t colA = (uint32_t)((lane >> 4) << 4);
    int rowB = wn * 32 + (lane & 7) + (lane >> 4) * 8;
    uint32_t colB = (uint32_t)(((lane >> 3) & 1) << 4);

    float acc[4][4][4];
    #pragma unroll
    for (int a = 0; a < 4; a++)
        #pragma unroll
        for (int b = 0; b < 4; b++)
            #pragma unroll
            for (int c = 0; c < 4; c++) acc[a][b][c] = 0.f;

    auto load_stage = [&](int kt, int buf) {
        uint32_t sA = sb + buf * STAGE_BYTES;
        uint32_t sB = sA + 16384;
        int kb = kt * 64;
        #pragma unroll
        for (int i = 0; i < 4; i++) {
            int row = ldrow + i * 32;
            uint32_t off = (uint32_t)(row * 128 + ldc * 16);
            off ^= (off >> 3) & 0x70;
            cpasync16(sA + off, Abase + (size_t)row * DQ + kb + ldc * 8);
            cpasync16(sB + off, Bbase + (size_t)row * DQ + kb + ldc * 8);
        }
        CP_COMMIT();
    };

    load_stage(0, 0);
    load_stage(1, 1);

    for (int kt = 0; kt < GK_TILES; kt++) {
        int buf = kt % 3;
        if (kt < GK_TILES - 1) asm volatile("cp.async.wait_group 1;" ::: "memory");
        else                   asm volatile("cp.async.wait_group 0;" ::: "memory");
        __syncthreads();
        if (kt + 2 < GK_TILES) load_stage(kt + 2, (kt + 2) % 3);

        uint32_t sA = sb + buf * STAGE_BYTES;
        uint32_t sB = sA + 16384;
        #pragma unroll
        for (int ks = 0; ks < 4; ks++) {
            uint32_t af[4][4], bf[4][2];
            #pragma unroll
            for (int mt = 0; mt < 4; mt++) {
                uint32_t off = (uint32_t)((rowA + mt * 16) * 128) + (uint32_t)(ks * 32) + colA;
                off ^= (off >> 3) & 0x70;
                ldsm_x4(af[mt][0], af[mt][1], af[mt][2], af[mt][3], sA + off);
            }
            #pragma unroll
            for (int p = 0; p < 2; p++) {
                uint32_t off = (uint32_t)((rowB + p * 16) * 128) + (uint32_t)(ks * 32) + colB;
                off ^= (off >> 3) & 0x70;
                ldsm_x4(bf[2*p][0], bf[2*p][1], bf[2*p+1][0], bf[2*p+1][1], sB + off);
            }
            #pragma unroll
            for (int mt = 0; mt < 4; mt++)
                #pragma unroll
                for (int nt = 0; nt < 4; nt++)
                    mma_bf16(acc[mt][nt], af[mt], bf[nt]);
        }
    }

    float sw = g_wscale[proj];
    #pragma unroll
    for (int mt = 0; mt < 4; mt++) {
        int mrow0 = blockIdx.x * 128 + wm * 64 + mt * 16 + gid;
        #pragma unroll
        for (int half = 0; half < 2; half++) {
            int mrow = mrow0 + half * 8;
            float sx = ((proj < 4) ? g_xscale[proj * MROWS + mrow] : g_xscale5[mrow]) * sw;
            #pragma unroll
            for (int nt = 0; nt < 4; nt++) {
                int ncol = blockIdx.y * 128 + wn * 32 + nt * 8 + tig * 2;
                float2 v;
                v.x = acc[mt][nt][half * 2]     * sx;
                v.y = acc[mt][nt][half * 2 + 1] * sx;
                float* dst;
                if (proj == 4)      dst = out_final + (size_t)mrow * DQ + ncol;
                else if (proj == 3) dst = g_gate + (size_t)mrow * DQ + ncol;
                else {
                    int b = mrow >> 11, t = mrow & (TQ - 1);
                    int h = ncol >> 6, s0 = ncol & 63;
                    float* basep = (proj == 0) ? g_r : (proj == 1) ? g_k : g_v;
                    dst = basep + (((size_t)(b * HQ + h) * TQ) + t) * SQ + s0;
                }
                *(float2*)dst = v;
            }
        }
    }
}

// ---------------- WKV pass A: per-chunk R_c[s][o] -----------------------------
__global__ void __launch_bounds__(256) wkv_rc_kernel(const float* __restrict__ log_decay) {
    __shared__ float ksm[4096], vsm[4096];
    int c = blockIdx.x, bh = blockIdx.y, h = bh & (HQ - 1);
    int tid = threadIdx.x;
    int s = tid >> 2, og = (tid & 3) * 16;
    size_t base = ((size_t)bh * TQ + (size_t)c * CQ) * SQ;

    #pragma unroll
    for (int j = 0; j < 4; j++) {
        int e = tid + j * 256;
        *(float4*)&ksm[e * 4] = *(const float4*)&g_k[base + e * 4];
        *(float4*)&vsm[e * 4] = *(const float4*)&g_v[base + e * 4];
    }
    float ws = expf(-expf(log_decay[h * 64 + s]));
    __syncthreads();

    float4 R0 = {0,0,0,0}, R1 = {0,0,0,0}, R2 = {0,0,0,0}, R3 = {0,0,0,0};
    float pw = 1.f;
    #pragma unroll 4
    for (int t = CQ - 1; t >= 0; t--) {
        float a = pw * ksm[t * 64 + s];
        const float4* vp = (const float4*)&vsm[t * 64 + og];
        float4 v0 = vp[0], v1 = vp[1], v2 = vp[2], v3 = vp[3];
        R0.x = fmaf(a, v0.x, R0.x); R0.y = fmaf(a, v0.y, R0.y);
        R0.z = fmaf(a, v0.z, R0.z); R0.w = fmaf(a, v0.w, R0.w);
        R1.x = fmaf(a, v1.x, R1.x); R1.y = fmaf(a, v1.y, R1.y);
        R1.z = fmaf(a, v1.z, R1.z); R1.w = fmaf(a, v1.w, R1.w);
        R2.x = fmaf(a, v2.x, R2.x); R2.y = fmaf(a, v2.y, R2.y);
        R2.z = fmaf(a, v2.z, R2.z); R2.w = fmaf(a, v2.w, R2.w);
        R3.x = fmaf(a, v3.x, R3.x); R3.y = fmaf(a, v3.y, R3.y);
        R3.z = fmaf(a, v3.z, R3.z); R3.w = fmaf(a, v3.w, R3.w);
        pw *= ws;
    }
    float* dst = g_state + ((size_t)bh * NCH + c) * 4096 + s * 64 + og;
    ((float4*)dst)[0] = R0; ((float4*)dst)[1] = R1;
    ((float4*)dst)[2] = R2; ((float4*)dst)[3] = R3;
}

// ---------------- WKV pass B: sequential state scan per bh --------------------
__global__ void __launch_bounds__(256) wkv_scan_kernel(const float* __restrict__ log_decay) {
    int bh = blockIdx.x, h = bh & (HQ - 1);
    int tid = threadIdx.x;
    int s = tid >> 2;
    float lw = -expf(log_decay[h * 64 + s]);
    float wC = expf(64.f * lw);
    float4 S0 = {0,0,0,0}, S1 = {0,0,0,0}, S2 = {0,0,0,0}, S3 = {0,0,0,0};
    float* base = g_state + (size_t)bh * NCH * 4096 + (size_t)tid * 16;
    #pragma unroll 1
    for (int c = 0; c < NCH; c++) {
        float4* p = (float4*)(base + (size_t)c * 4096);
        float4 R0 = p[0], R1 = p[1], R2 = p[2], R3 = p[3];
        p[0] = S0; p[1] = S1; p[2] = S2; p[3] = S3;
        S0.x = fmaf(wC, S0.x, R0.x); S0.y = fmaf(wC, S0.y, R0.y);
        S0.z = fmaf(wC, S0.z, R0.z); S0.w = fmaf(wC, S0.w, R0.w);
        S1.x = fmaf(wC, S1.x, R1.x); S1.y = fmaf(wC, S1.y, R1.y);
        S1.z = fmaf(wC, S1.z, R1.z); S1.w = fmaf(wC, S1.w, R1.w);
        S2.x = fmaf(wC, S2.x, R2.x); S2.y = fmaf(wC, S2.y, R2.y);
        S2.z = fmaf(wC, S2.z, R2.z); S2.w = fmaf(wC, S2.w, R2.w);
        S3.x = fmaf(wC, S3.x, R3.x); S3.y = fmaf(wC, S3.y, R3.y);
        S3.z = fmaf(wC, S3.z, R3.z); S3.w = fmaf(wC, S3.w, R3.w);
    }
}

// ---------------- WKV pass C: per-chunk outputs -------------------------------
// grid (NCH, 64bh, 2og); block 256 = 8 warps x 4 outputs; 8 lanes x 8 states.
__global__ void __launch_bounds__(256) wkv_out_kernel(
        const float* __restrict__ log_decay, const float* __restrict__ uu) {
    extern __shared__ float sm[];
    float* rs  = sm;            // 4096
    float* ksm = sm + 4096;     // 4096
    float* vsm = sm + 8192;     // 2048
    float* scm = sm + 10240;    // 2048
    int c = blockIdx.x, bh = blockIdx.y, og2 = blockIdx.z, h = bh & (HQ - 1);
    int tid = threadIdx.x, warp = tid >> 5, lane = tid & 31;
    int ol = lane >> 3;
    int olocal = warp * 4 + ol;
    int o = og2 * 32 + olocal;
    int sl = lane & 7;
    int sbase = sl * 8;
    size_t base = ((size_t)bh * TQ + (size_t)c * CQ) * SQ;
    const float* stb = g_state + ((size_t)bh * NCH + c) * 4096;

    #pragma unroll
    for (int j = 0; j < 4; j++) {
        int e = tid + j * 256;
        *(float4*)&rs[e * 4]  = *(const float4*)&g_r[base + e * 4];
        *(float4*)&ksm[e * 4] = *(const float4*)&g_k[base + e * 4];
    }
    #pragma unroll
    for (int j = 0; j < 2; j++) {
        int e = tid + j * 256;           // 512 float4 chunks each for vsm/scm
        int tt = e >> 3, c4 = (e & 7) * 4;
        *(float4*)&vsm[tt * 32 + c4] =
            *(const float4*)&g_v[base + (size_t)tt * SQ + og2 * 32 + c4];
        *(float4*)&scm[tt * 32 + c4] =
            *(const float4*)&stb[(size_t)tt * SQ + og2 * 32 + c4];
    }

    ULL w_[4], winv[4], wpt[4], u2[4];
    #pragma unroll
    for (int j = 0; j < 4; j++) {
        int s0 = sbase + j * 2;
        float lw0 = -expf(log_decay[h * 64 + s0]);
        float lw1 = -expf(log_decay[h * 64 + s0 + 1]);
        w_[j]   = pk2(expf(lw0), expf(lw1));
        winv[j] = pk2(expf(-lw0), expf(-lw1));
        wpt[j]  = pk2(expf(64.f * lw0), expf(64.f * lw1));   // w^{t+1} at t=63
        u2[j]   = pk2(expf(uu[h * 64 + s0]), expf(uu[h * 64 + s0 + 1]));
    }
    __syncthreads();

    ULL S[4], Q[4] = {0ull, 0ull, 0ull, 0ull};
    #pragma unroll
    for (int j = 0; j < 4; j++)
        S[j] = pk2(scm[(sbase + 2*j) * 32 + olocal], scm[(sbase + 2*j + 1) * 32 + olocal]);

    #pragma unroll 4
    for (int t = CQ - 1; t >= 0; t--) {
        float vt = vsm[t * 32 + olocal];
        ULL vtt = pk2(vt, vt);
        ulonglong2 kk0 = *(const ulonglong2*)(ksm + t * 64 + sbase);
        ulonglong2 kk1 = *(const ulonglong2*)(ksm + t * 64 + sbase + 4);
        ulonglong2 rr0 = *(const ulonglong2*)(rs  + t * 64 + sbase);
        ulonglong2 rr1 = *(const ulonglong2*)(rs  + t * 64 + sbase + 4);
        ULL kv0 = mul2(kk0.x, vtt), kv1 = mul2(kk0.y, vtt);
        ULL kv2 = mul2(kk1.x, vtt), kv3 = mul2(kk1.y, vtt);
        Q[0] = fma2(w_[0], Q[0], kv0); Q[1] = fma2(w_[1], Q[1], kv1);
        Q[2] = fma2(w_[2], Q[2], kv2); Q[3] = fma2(w_[3], Q[3], kv3);
        ULL a0 = fma2(u2[0], kv0, Q[0]); a0 = fma2(wpt[0], S[0], a0);
        ULL a1 = fma2(u2[1], kv1, Q[1]); a1 = fma2(wpt[1], S[1], a1);
        ULL a2 = fma2(u2[2], kv2, Q[2]); a2 = fma2(wpt[2], S[2], a2);
        ULL a3 = fma2(u2[3], kv3, Q[3]); a3 = fma2(wpt[3], S[3], a3);
        ULL p2 = mul2(rr0.x, a0);
        p2 = fma2(rr0.y, a1, p2);
        p2 = fma2(rr1.x, a2, p2);
        p2 = fma2(rr1.y, a3, p2);
        float pl, ph; upk2(p2, pl, ph);
        float pv = pl + ph;
        wpt[0] = mul2(wpt[0], winv[0]); wpt[1] = mul2(wpt[1], winv[1]);
        wpt[2] = mul2(wpt[2], winv[2]); wpt[3] = mul2(wpt[3], winv[3]);
        pv += __shfl_xor_sync(0xffffffffu, pv, 4);
        pv += __shfl_xor_sync(0xffffffffu, pv, 2);
        pv += __shfl_xor_sync(0xffffffffu, pv, 1);
        if (sl == 0) g_y[base + (size_t)t * SQ + o] = pv;
    }
}

// ---------------- GroupNorm + SiLU gate + LN + quant (64 threads per row) -----
__global__ void __launch_bounds__(256) gngate_kernel(
        const float* __restrict__ gn_g, const float* __restrict__ gn_b,
        const float* __restrict__ ln_g, const float* __restrict__ ln_b) {
    __shared__ float shst[4][2][2];
    __shared__ float shab[4][2];
    int tid = threadIdx.x;
    int rg = tid >> 6, lt = tid & 63, wip = (tid >> 5) & 1, lane = tid & 31;
    int m = blockIdx.x * 4 + rg;
    int b = m >> 11, t = m & (TQ - 1);
    int h = lt >> 2, s0 = (lt & 3) * 16;
    int d0 = lt * 16;

    float val[16];
    const float* yp = g_y + ((size_t)(b * HQ + h) * TQ + t) * SQ + s0;
    float gs = 0.f, gq = 0.f;
    #pragma unroll
    for (int j = 0; j < 4; j++) {
        float4 a = *(const float4*)(yp + j * 4);
        val[j*4+0] = a.x; val[j*4+1] = a.y; val[j*4+2] = a.z; val[j*4+3] = a.w;
        gs += a.x + a.y + a.z + a.w;
        gq += a.x*a.x + a.y*a.y + a.z*a.z + a.w*a.w;
    }
    gs += __shfl_xor_sync(0xffffffffu, gs, 1); gq += __shfl_xor_sync(0xffffffffu, gq, 1);
    gs += __shfl_xor_sync(0xffffffffu, gs, 2); gq += __shfl_xor_sync(0xffffffffu, gq, 2);
    float gm = gs * (1.f / 64.f);
    float gvar = fmaxf(gq * (1.f / 64.f) - gm * gm, 0.f);
    float rstd = rsqrtf(gvar + 1e-5f);

    const float* gp = g_gate + (size_t)m * DQ + d0;
    float ssum = 0.f, ssq = 0.f;
    #pragma unroll
    for (int j = 0; j < 4; j++) {
        float4 gg = *(const float4*)(gp + j * 4);
        float4 gn4 = *(const float4*)(gn_g + d0 + j * 4);
        float4 gb4 = *(const float4*)(gn_b + d0 + j * 4);
        float gvv[4] = {gg.x, gg.y, gg.z, gg.w};
        float ga[4] = {gn4.x, gn4.y, gn4.z, gn4.w};
        float gbv[4] = {gb4.x, gb4.y, gb4.z, gb4.w};
        #pragma unroll
        for (int q = 0; q < 4; q++) {
            float yn = (val[j*4+q] - gm) * rstd * ga[q] + gbv[q];
            float v = yn * (gvv[q] / (1.f + expf(-gvv[q])));
            val[j*4+q] = v; ssum += v; ssq += v * v;
        }
    }
    ssum = warpsum(ssum); ssq = warpsum(ssq);
    if (lane == 0) { shst[rg][wip][0] = ssum; shst[rg][wip][1] = ssq; }
    __syncthreads();
    float ts  = shst[rg][0][0] + shst[rg][1][0];
    float ts2 = shst[rg][0][1] + shst[rg][1][1];
    float mean = ts * (1.f / DQ);
    float var = fmaxf(ts2 * (1.f / DQ) - mean * mean, 0.f);
    float lrstd = rsqrtf(var + 1e-5f);
    const float* lgp = ln_g + 4 * DQ + d0;
    const float* lbp = ln_b + 4 * DQ + d0;
    float sa = 0.f;
    #pragma unroll
    for (int j = 0; j < 4; j++) {
        float4 lg = *(const float4*)(lgp + j * 4);
        float4 lb = *(const float4*)(lbp + j * 4);
        float v0 = (val[j*4+0] - mean) * lrstd * lg.x + lb.x;
        float v1 = (val[j*4+1] - mean) * lrstd * lg.y + lb.y;
        float v2 = (val[j*4+2] - mean) * lrstd * lg.z + lb.z;
        float v3 = (val[j*4+3] - mean) * lrstd * lg.w + lb.w;
        val[j*4+0] = v0; val[j*4+1] = v1; val[j*4+2] = v2; val[j*4+3] = v3;
        sa += fabsf(v0) + fabsf(v1) + fabsf(v2) + fabsf(v3);
    }
    sa = warpsum(sa);
    if (lane == 0) shab[rg][wip] = sa;
    __syncthreads();
    float ma = (shab[rg][0] + shab[rg][1]) * (1.f / DQ);
    float scale = fmaxf(ma, 1e-8f) * 2.5f / 127.f;
    float inv = 1.f / scale;
    size_t off = (size_t)m * DQ + d0;
    #pragma unroll
    for (int g = 0; g < 2; g++) {
        uint4 u;
        float q0 = rintf(fminf(fmaxf(val[g*8+0] * inv, -127.f), 127.f));
        float q1 = rintf(fminf(fmaxf(val[g*8+1] * inv, -127.f), 127.f));
        float q2 = rintf(fminf(fmaxf(val[g*8+2] * inv, -127.f), 127.f));
        float q3 = rintf(fminf(fmaxf(val[g*8+3] * inv, -127.f), 127.f));
        float q4 = rintf(fminf(fmaxf(val[g*8+4] * inv, -127.f), 127.f));
        float q5 = rintf(fminf(fmaxf(val[g*8+5] * inv, -127.f), 127.f));
        float q6 = rintf(fminf(fmaxf(val[g*8+6] * inv, -127.f), 127.f));
        float q7 = rintf(fminf(fmaxf(val[g*8+7] * inv, -127.f), 127.f));
        u.x = bf2bits(q0, q1); u.y = bf2bits(q2, q3);
        u.z = bf2bits(q4, q5); u.w = bf2bits(q6, q7);
        *(uint4*)(g_xq5 + off + g * 8) = u;
    }
    if (lt == 0) g_xscale5[m] = scale;
}

// ---------------- launcher ----------------------------------------------------
#define GEMM_SMEM (3 * STAGE_BYTES + 1024)
#define WKVC_SMEM (12288 * 4)

extern "C" void kernel_launch(void* const* d_in, const int* in_sizes, int n_in,
                              void* d_out, int out_size) {
    const float* x         = (const float*)d_in[0];
    const float* mu_r      = (const float*)d_in[1];
    const float* mu_k      = (const float*)d_in[2];
    const float* mu_v      = (const float*)d_in[3];
    const float* mu_g      = (const float*)d_in[4];
    const float* log_decay = (const float*)d_in[5];
    const float* u         = (const float*)d_in[6];
    const float* proj_w    = (const float*)d_in[7];
    const float* ln_g      = (const float*)d_in[8];
    const float* ln_b      = (const float*)d_in[9];
    const float* gn_g      = (const float*)d_in[10];
    const float* gn_b      = (const float*)d_in[11];
    float* out = (float*)d_out;

    cudaFuncSetAttribute(gemm_mma_kernel, cudaFuncAttributeMaxDynamicSharedMemorySize, GEMM_SMEM);
    cudaFuncSetAttribute(wkv_out_kernel, cudaFuncAttributeMaxDynamicSharedMemorySize, WKVC_SMEM);

    wq_scale_kernel<<<dim3(64, 5), 256>>>(proj_w);
    quant_lnq4_kernel<<<5120 + 2048, 256>>>(proj_w, x, mu_r, mu_k, mu_v, mu_g, ln_g, ln_b);
    gemm_mma_kernel<<<dim3(64, 8, 4), 256, GEMM_SMEM>>>(nullptr);
    wkv_rc_kernel<<<dim3(NCH, 64), 256>>>(log_decay);
    wkv_scan_kernel<<<64, 256>>>(log_decay);
    wkv_out_kernel<<<dim3(NCH, 64, 2), 256, WKVC_SMEM>>>(log_decay, u);
    gngate_kernel<<<2048, 256>>>(gn_g, gn_b, ln_g, ln_b);
    gemm_mma_kernel<<<dim3(64, 8, 1), 256, GEMM_SMEM>>>(out);
}

// round 15
// speedup vs baseline: 1.4399x; 1.4399x over previous
#include <cuda_runtime.h>
#include <cuda_bf16.h>
#include <cstdint>

#define BQ 4
#define TQ 2048
#define DQ 1024
#define HQ 16
#define SQ 64
#define CQ 64
#define MROWS (BQ*TQ)   /* 8192 */

typedef unsigned long long ULL;

// ---------------- device scratch ----------------------------------------------
__device__ __align__(256) __nv_bfloat16 g_wq[5u*1024u*1024u];
__device__ float         g_wscale[5];
__device__ float         g_partial[5*64];
__device__ unsigned      g_cnt[5];
__device__ __align__(256) __nv_bfloat16 g_xq[4u*MROWS*DQ];
__device__ float         g_xscale[4*MROWS];
__device__ __align__(256) float g_r[MROWS*DQ];
__device__ __align__(256) float g_k[MROWS*DQ];
__device__ __align__(256) float g_v[MROWS*DQ];
__device__ __align__(256) float g_gate[MROWS*DQ];
__device__ __align__(256) float g_y[MROWS*DQ];
__device__ __align__(256) __nv_bfloat16 g_xq5[MROWS*DQ];
__device__ float         g_xscale5[MROWS];

// ---------------- PTX helpers --------------------------------------------------
__device__ __forceinline__ uint32_t smem_u32(const void* p) {
    uint32_t a;
    asm("{ .reg .u64 t; cvta.to.shared.u64 t, %1; cvt.u32.u64 %0, t; }" : "=r"(a) : "l"(p));
    return a;
}
__device__ __forceinline__ void cpasync16(uint32_t saddr, const void* g) {
    asm volatile("cp.async.cg.shared.global [%0], [%1], 16;" :: "r"(saddr), "l"(g) : "memory");
}
#define CP_COMMIT() asm volatile("cp.async.commit_group;" ::: "memory")
#define CP_WAIT0()  asm volatile("cp.async.wait_group 0;" ::: "memory")

__device__ __forceinline__ void ldsm_x4(uint32_t& r0, uint32_t& r1, uint32_t& r2, uint32_t& r3,
                                        uint32_t addr) {
    asm volatile("ldmatrix.sync.aligned.m8n8.x4.shared.b16 {%0,%1,%2,%3}, [%4];"
        : "=r"(r0), "=r"(r1), "=r"(r2), "=r"(r3) : "r"(addr));
}
__device__ __forceinline__ void mma_bf16(float c[4], const uint32_t a[4], const uint32_t b[2]) {
    asm volatile(
        "mma.sync.aligned.m16n8k16.row.col.f32.bf16.bf16.f32 "
        "{%0,%1,%2,%3}, {%4,%5,%6,%7}, {%8,%9}, {%0,%1,%2,%3};\n"
        : "+f"(c[0]), "+f"(c[1]), "+f"(c[2]), "+f"(c[3])
        : "r"(a[0]), "r"(a[1]), "r"(a[2]), "r"(a[3]), "r"(b[0]), "r"(b[1]));
}

__device__ __forceinline__ ULL pk2(float a, float b) {
    ULL r; asm("mov.b64 %0, {%1, %2};" : "=l"(r) : "f"(a), "f"(b)); return r;
}
__device__ __forceinline__ void upk2(ULL v, float& a, float& b) {
    asm("mov.b64 {%0, %1}, %2;" : "=f"(a), "=f"(b) : "l"(v));
}
__device__ __forceinline__ ULL fma2(ULL a, ULL b, ULL c) {
    ULL d; asm("fma.rn.f32x2 %0, %1, %2, %3;" : "=l"(d) : "l"(a), "l"(b), "l"(c)); return d;
}
__device__ __forceinline__ ULL mul2(ULL a, ULL b) {
    ULL d; asm("mul.rn.f32x2 %0, %1, %2;" : "=l"(d) : "l"(a), "l"(b)); return d;
}

__device__ __forceinline__ float warpsum(float v) {
    #pragma unroll
    for (int o = 16; o; o >>= 1) v += __shfl_xor_sync(0xffffffffu, v, o);
    return v;
}
__device__ __forceinline__ uint32_t bf2bits(float a, float b) {
    __nv_bfloat162 h(__float2bfloat16(a), __float2bfloat16(b));
    return *(uint32_t*)&h;
}

// ---------------- weight scale (fused two-stage via atomic counter) -----------
__global__ void wq_scale_kernel(const float* __restrict__ w) {
    __shared__ float sh[8];
    __shared__ bool last;
    int z = blockIdx.y, blk = blockIdx.x, tid = threadIdx.x;
    const float* base = w + (size_t)z * 1048576u + (size_t)blk * 16384u;
    float s = 0.f;
    #pragma unroll
    for (int j = 0; j < 16; j++) {
        float4 v = *(const float4*)(base + (tid + j * 256) * 4);
        s += fabsf(v.x) + fabsf(v.y) + fabsf(v.z) + fabsf(v.w);
    }
    s = warpsum(s);
    if ((tid & 31) == 0) sh[tid >> 5] = s;
    __syncthreads();
    if (tid == 0) {
        float t = 0.f;
        #pragma unroll
        for (int i = 0; i < 8; i++) t += sh[i];
        g_partial[z * 64 + blk] = t;
        __threadfence();
        unsigned prev = atomicAdd(&g_cnt[z], 1u);
        last = (prev == 63u);
    }
    __syncthreads();
    if (last && tid < 32) {
        float t = g_partial[z * 64 + tid] + g_partial[z * 64 + 32 + tid];
        t = warpsum(t);
        if (tid == 0) {
            g_wscale[z] = fmaxf(t * (1.f / 1048576.f), 1e-8f);
            g_cnt[z] = 0u;
        }
    }
}

// ---------------- fused: weight quant (blocks 0..5119) + lnq4 (5120..7167) ----
__global__ void __launch_bounds__(256) quant_lnq4_kernel(
        const float* __restrict__ w, const float* __restrict__ x,
        const float* __restrict__ mu_r, const float* __restrict__ mu_k,
        const float* __restrict__ mu_v, const float* __restrict__ mu_g,
        const float* __restrict__ ln_g, const float* __restrict__ ln_b) {
    __shared__ float shst[4][2][2];
    __shared__ float shab[4][2];
    int tid = threadIdx.x;

    if (blockIdx.x < 5120) {
        int idx = (blockIdx.x * 256 + tid) * 4;
        int z = idx >> 20;
        float s = g_wscale[z];
        float4 wv = *(const float4*)(w + idx);
        float vv[4] = {wv.x, wv.y, wv.z, wv.w};
        __nv_bfloat16 q[4];
        #pragma unroll
        for (int j = 0; j < 4; j++) {
            float wn = vv[j] / s;
            wn = fminf(fmaxf(wn, -1.f), 1.f);
            q[j] = __float2bfloat16(rintf(wn));
        }
        *(__nv_bfloat162*)(g_wq + idx)     = __nv_bfloat162(q[0], q[1]);
        *(__nv_bfloat162*)(g_wq + idx + 2) = __nv_bfloat162(q[2], q[3]);
        return;
    }

    int blk = blockIdx.x - 5120;
    int rg = tid >> 6, lt = tid & 63, wip = (tid >> 5) & 1, lane = tid & 31;
    int m = blk * 4 + rg;
    int d0 = lt * 16;
    const float* xr = x + (size_t)m * DQ + d0;
    bool hp = (m & (TQ - 1)) != 0;
    const float* mus[4] = {mu_r, mu_k, mu_v, mu_g};

    float xv[16], dx[16];
    #pragma unroll
    for (int j = 0; j < 4; j++) {
        float4 a = *(const float4*)(xr + j * 4);
        float4 p = hp ? *(const float4*)(xr - DQ + j * 4) : make_float4(0.f, 0.f, 0.f, 0.f);
        xv[j*4+0] = a.x; xv[j*4+1] = a.y; xv[j*4+2] = a.z; xv[j*4+3] = a.w;
        dx[j*4+0] = p.x - a.x; dx[j*4+1] = p.y - a.y;
        dx[j*4+2] = p.z - a.z; dx[j*4+3] = p.w - a.w;
    }

    #pragma unroll 1
    for (int i = 0; i < 4; i++) {
        float inp[16];
        float s = 0.f, s2 = 0.f;
        const float* mup = mus[i] + d0;
        #pragma unroll
        for (int j = 0; j < 4; j++) {
            float4 mu = *(const float4*)(mup + j * 4);
            float v0 = fmaf(dx[j*4+0], mu.x, xv[j*4+0]);
            float v1 = fmaf(dx[j*4+1], mu.y, xv[j*4+1]);
            float v2 = fmaf(dx[j*4+2], mu.z, xv[j*4+2]);
            float v3 = fmaf(dx[j*4+3], mu.w, xv[j*4+3]);
            inp[j*4+0] = v0; inp[j*4+1] = v1; inp[j*4+2] = v2; inp[j*4+3] = v3;
            s += v0 + v1 + v2 + v3;
            s2 += v0*v0 + v1*v1 + v2*v2 + v3*v3;
        }
        s = warpsum(s); s2 = warpsum(s2);
        if (lane == 0) { shst[rg][wip][0] = s; shst[rg][wip][1] = s2; }
        __syncthreads();
        float ts  = shst[rg][0][0] + shst[rg][1][0];
        float ts2 = shst[rg][0][1] + shst[rg][1][1];
        float mean = ts * (1.f / DQ);
        float var = fmaxf(ts2 * (1.f / DQ) - mean * mean, 0.f);
        float rstd = rsqrtf(var + 1e-5f);
        const float* gp = ln_g + i * DQ + d0;
        const float* bp = ln_b + i * DQ + d0;
        float sa = 0.f;
        #pragma unroll
        for (int j = 0; j < 4; j++) {
            float4 gg = *(const float4*)(gp + j * 4);
            float4 bb = *(const float4*)(bp + j * 4);
            float v0 = (inp[j*4+0] - mean) * rstd * gg.x + bb.x;
            float v1 = (inp[j*4+1] - mean) * rstd * gg.y + bb.y;
            float v2 = (inp[j*4+2] - mean) * rstd * gg.z + bb.z;
            float v3 = (inp[j*4+3] - mean) * rstd * gg.w + bb.w;
            inp[j*4+0] = v0; inp[j*4+1] = v1; inp[j*4+2] = v2; inp[j*4+3] = v3;
            sa += fabsf(v0) + fabsf(v1) + fabsf(v2) + fabsf(v3);
        }
        sa = warpsum(sa);
        if (lane == 0) shab[rg][wip] = sa;
        __syncthreads();
        float ma = (shab[rg][0] + shab[rg][1]) * (1.f / DQ);
        float scale = fmaxf(ma, 1e-8f) * 2.5f / 127.f;
        float inv = 1.f / scale;
        size_t off = (size_t)i * MROWS * DQ + (size_t)m * DQ + d0;
        #pragma unroll
        for (int g = 0; g < 2; g++) {
            uint4 u;
            float q0 = rintf(fminf(fmaxf(inp[g*8+0] * inv, -127.f), 127.f));
            float q1 = rintf(fminf(fmaxf(inp[g*8+1] * inv, -127.f), 127.f));
            float q2 = rintf(fminf(fmaxf(inp[g*8+2] * inv, -127.f), 127.f));
            float q3 = rintf(fminf(fmaxf(inp[g*8+3] * inv, -127.f), 127.f));
            float q4 = rintf(fminf(fmaxf(inp[g*8+4] * inv, -127.f), 127.f));
            float q5 = rintf(fminf(fmaxf(inp[g*8+5] * inv, -127.f), 127.f));
            float q6 = rintf(fminf(fmaxf(inp[g*8+6] * inv, -127.f), 127.f));
            float q7 = rintf(fminf(fmaxf(inp[g*8+7] * inv, -127.f), 127.f));
            u.x = bf2bits(q0, q1); u.y = bf2bits(q2, q3);
            u.z = bf2bits(q4, q5); u.w = bf2bits(q6, q7);
            *(uint4*)(g_xq + off + g * 8) = u;
        }
        if (lt == 0) g_xscale[i * MROWS + m] = scale;
    }
}

// ---------------- mma.sync bf16 GEMM with ldmatrix + cp.async pipeline --------
#define GK_TILES 16
#define STAGE_BYTES 32768

__global__ void __launch_bounds__(256, 2) gemm_mma_kernel(float* __restrict__ out_final) {
    extern __shared__ char smem_raw[];
    uint32_t sb = (smem_u32(smem_raw) + 1023u) & ~1023u;
    int tid = threadIdx.x, warp = tid >> 5, lane = tid & 31;
    int wm = warp >> 2, wn = warp & 3;
    int gid = lane >> 2, tig = lane & 3;

    int proj = (gridDim.z > 1) ? blockIdx.z : 4;
    const __nv_bfloat16* Ag = (proj < 4) ? (g_xq + (size_t)proj * MROWS * DQ) : g_xq5;
    const __nv_bfloat16* Bg = g_wq + (size_t)proj * DQ * DQ;
    const __nv_bfloat16* Abase = Ag + (size_t)blockIdx.x * 128 * DQ;
    const __nv_bfloat16* Bbase = Bg + (size_t)blockIdx.y * 128 * DQ;

    int ldrow = tid >> 3, ldc = tid & 7;
    int rowA = wm * 64 + (lane & 7) + ((lane >> 3) & 1) * 8;
    uint32_t colA = (uint32_t)((lane >> 4) << 4);
    int rowB = wn * 32 + (lane & 7) + (lane >> 4) * 8;
    uint32_t colB = (uint32_t)(((lane >> 3) & 1) << 4);

    float acc[4][4][4];
    #pragma unroll
    for (int a = 0; a < 4; a++)
        #pragma unroll
        for (int b = 0; b < 4; b++)
            #pragma unroll
            for (int c = 0; c < 4; c++) acc[a][b][c] = 0.f;

    auto load_stage = [&](int kt, int buf) {
        uint32_t sA = sb + buf * STAGE_BYTES;
        uint32_t sB = sA + 16384;
        int kb = kt * 64;
        #pragma unroll
        for (int i = 0; i < 4; i++) {
            int row = ldrow + i * 32;
            uint32_t off = (uint32_t)(row * 128 + ldc * 16);
            off ^= (off >> 3) & 0x70;
            cpasync16(sA + off, Abase + (size_t)row * DQ + kb + ldc * 8);
            cpasync16(sB + off, Bbase + (size_t)row * DQ + kb + ldc * 8);
        }
        CP_COMMIT();
    };

    load_stage(0, 0);
    load_stage(1, 1);

    for (int kt = 0; kt < GK_TILES; kt++) {
        int buf = kt % 3;
        if (kt < GK_TILES - 1) asm volatile("cp.async.wait_group 1;" ::: "memory");
        else                   asm volatile("cp.async.wait_group 0;" ::: "memory");
        __syncthreads();
        if (kt + 2 < GK_TILES) load_stage(kt + 2, (kt + 2) % 3);

        uint32_t sA = sb + buf * STAGE_BYTES;
        uint32_t sB = sA + 16384;
        #pragma unroll
        for (int ks = 0; ks < 4; ks++) {
            uint32_t af[4][4], bf[4][2];
            #pragma unroll
            for (int mt = 0; mt < 4; mt++) {
                uint32_t off = (uint32_t)((rowA + mt * 16) * 128) + (uint32_t)(ks * 32) + colA;
                off ^= (off >> 3) & 0x70;
                ldsm_x4(af[mt][0], af[mt][1], af[mt][2], af[mt][3], sA + off);
            }
            #pragma unroll
            for (int p = 0; p < 2; p++) {
                uint32_t off = (uint32_t)((rowB + p * 16) * 128) + (uint32_t)(ks * 32) + colB;
                off ^= (off >> 3) & 0x70;
                ldsm_x4(bf[2*p][0], bf[2*p][1], bf[2*p+1][0], bf[2*p+1][1], sB + off);
            }
            #pragma unroll
            for (int mt = 0; mt < 4; mt++)
                #pragma unroll
                for (int nt = 0; nt < 4; nt++)
                    mma_bf16(acc[mt][nt], af[mt], bf[nt]);
        }
    }

    float sw = g_wscale[proj];
    #pragma unroll
    for (int mt = 0; mt < 4; mt++) {
        int mrow0 = blockIdx.x * 128 + wm * 64 + mt * 16 + gid;
        #pragma unroll
        for (int half = 0; half < 2; half++) {
            int mrow = mrow0 + half * 8;
            float sx = ((proj < 4) ? g_xscale[proj * MROWS + mrow] : g_xscale5[mrow]) * sw;
            #pragma unroll
            for (int nt = 0; nt < 4; nt++) {
                int ncol = blockIdx.y * 128 + wn * 32 + nt * 8 + tig * 2;
                float2 v;
                v.x = acc[mt][nt][half * 2]     * sx;
                v.y = acc[mt][nt][half * 2 + 1] * sx;
                float* dst;
                if (proj == 4)      dst = out_final + (size_t)mrow * DQ + ncol;
                else if (proj == 3) dst = g_gate + (size_t)mrow * DQ + ncol;
                else {
                    int b = mrow >> 11, t = mrow & (TQ - 1);
                    int h = ncol >> 6, s0 = ncol & 63;
                    float* basep = (proj == 0) ? g_r : (proj == 1) ? g_k : g_v;
                    dst = basep + (((size_t)(b * HQ + h) * TQ) + t) * SQ + s0;
                }
                *(float2*)dst = v;
            }
        }
    }
}

// ---------------- WKV: monolithic, 16 states/lane, 8 outputs/warp -------------
// grid 128 = 64bh x 2og; block 128 = 4 warps x 8 outputs = 32 outputs.
// lane = sg*8 + ol: sg in 0..3 covers 16 states each; ol in 0..7.
#define WKV_BUF 10240   /* floats: rs 4096 + ksm 4096 + vsm 2048 */

__global__ void __launch_bounds__(128) wkv_kernel(
        const float* __restrict__ log_decay, const float* __restrict__ uu) {
    extern __shared__ float sm[];
    uint32_t smb = smem_u32(sm);
    int bh = blockIdx.x >> 1, og2 = blockIdx.x & 1, h = bh & (HQ - 1);
    int tid = threadIdx.x, warp = tid >> 5, lane = tid & 31;
    int sg = lane >> 3, ol = lane & 7;
    int olocal = warp * 8 + ol;
    int o = og2 * 32 + olocal;
    int sbase = sg * 16;
    size_t bhb = (size_t)bh * TQ * SQ;

    ULL w_[8], winv[8], wC[8], u2[8];
    #pragma unroll
    for (int j = 0; j < 8; j++) {
        int s0 = sbase + j * 2;
        float lw0 = -expf(log_decay[h * 64 + s0]);
        float lw1 = -expf(log_decay[h * 64 + s0 + 1]);
        w_[j]   = pk2(expf(lw0), expf(lw1));
        winv[j] = pk2(expf(-lw0), expf(-lw1));
        wC[j]   = pk2(expf(64.f * lw0), expf(64.f * lw1));
        u2[j]   = pk2(expf(uu[h * 64 + s0]), expf(uu[h * 64 + s0 + 1]));
    }
    ULL one2 = pk2(1.f, 1.f);
    ULL S[8];
    #pragma unroll
    for (int j = 0; j < 8; j++) S[j] = 0ull;

    auto prefetch = [&](int c, int pb) {
        size_t base = bhb + (size_t)c * CQ * SQ;
        uint32_t rsb  = smb + (uint32_t)pb * WKV_BUF * 4;
        uint32_t ksb  = rsb + 4096 * 4;
        uint32_t vsb  = ksb + 4096 * 4;
        #pragma unroll
        for (int j = 0; j < 8; j++) {
            int e = tid + j * 128;
            cpasync16(rsb + (uint32_t)e * 16, &g_r[base + (size_t)e * 4]);
            cpasync16(ksb + (uint32_t)e * 16, &g_k[base + (size_t)e * 4]);
        }
        #pragma unroll
        for (int j = 0; j < 4; j++) {
            int e = tid + j * 128;           // 512 float4 chunks
            int tt = e >> 3, c4 = (e & 7) * 4;
            cpasync16(vsb + (uint32_t)(tt * 32 + c4) * 4,
                      &g_v[base + (size_t)tt * SQ + og2 * 32 + c4]);
        }
        CP_COMMIT();
    };

    prefetch(0, 0);
    CP_WAIT0();
    __syncthreads();
    int p = 0;

    for (int c = 0; c < TQ / CQ; c++) {
        if (c + 1 < TQ / CQ) prefetch(c + 1, p ^ 1);
        float* rs  = sm + p * WKV_BUF;
        float* ksm = rs + 4096;
        float* vsm = ksm + 4096;
        size_t base = bhb + (size_t)c * CQ * SQ;

        ULL Q[8], R[8], pw[8], wpt[8];
        #pragma unroll
        for (int j = 0; j < 8; j++) {
            Q[j] = 0ull; R[j] = 0ull; pw[j] = one2; wpt[j] = wC[j];
        }
        #pragma unroll 2
        for (int t = CQ - 1; t >= 0; t--) {
            float vt = vsm[t * 32 + olocal];
            ULL vtt = pk2(vt, vt);
            const ulonglong2* kp = (const ulonglong2*)(ksm + t * 64 + sbase);
            const ulonglong2* rp = (const ulonglong2*)(rs  + t * 64 + sbase);
            ulonglong2 kk0 = kp[0], kk1 = kp[1], kk2 = kp[2], kk3 = kp[3];
            ulonglong2 rr0 = rp[0], rr1 = rp[1], rr2 = rp[2], rr3 = rp[3];
            ULL kv[8];
            kv[0] = mul2(kk0.x, vtt); kv[1] = mul2(kk0.y, vtt);
            kv[2] = mul2(kk1.x, vtt); kv[3] = mul2(kk1.y, vtt);
            kv[4] = mul2(kk2.x, vtt); kv[5] = mul2(kk2.y, vtt);
            kv[6] = mul2(kk3.x, vtt); kv[7] = mul2(kk3.y, vtt);
            ULL a[8];
            #pragma unroll
            for (int j = 0; j < 8; j++) {
                Q[j] = fma2(w_[j], Q[j], kv[j]);
                a[j] = fma2(u2[j], kv[j], Q[j]);
                a[j] = fma2(wpt[j], S[j], a[j]);
            }
            ULL p2 = mul2(rr0.x, a[0]);
            p2 = fma2(rr0.y, a[1], p2);
            p2 = fma2(rr1.x, a[2], p2);
            p2 = fma2(rr1.y, a[3], p2);
            p2 = fma2(rr2.x, a[4], p2);
            p2 = fma2(rr2.y, a[5], p2);
            p2 = fma2(rr3.x, a[6], p2);
            p2 = fma2(rr3.y, a[7], p2);
            float pl, ph; upk2(p2, pl, ph);
            float pv = pl + ph;
            #pragma unroll
            for (int j = 0; j < 8; j++) {
                R[j] = fma2(pw[j], kv[j], R[j]);
                pw[j] = mul2(pw[j], w_[j]);
                wpt[j] = mul2(wpt[j], winv[j]);
            }
            pv += __shfl_xor_sync(0xffffffffu, pv, 8);
            pv += __shfl_xor_sync(0xffffffffu, pv, 16);
            if (sg == 0) g_y[base + (size_t)t * SQ + o] = pv;
        }
        #pragma unroll
        for (int j = 0; j < 8; j++) S[j] = fma2(wC[j], S[j], R[j]);
        if (c + 1 < TQ / CQ) CP_WAIT0();
        __syncthreads();
        p ^= 1;
    }
}

// ---------------- GroupNorm + SiLU gate + LN + quant (64 threads per row) -----
__global__ void __launch_bounds__(256) gngate_kernel(
        const float* __restrict__ gn_g, const float* __restrict__ gn_b,
        const float* __restrict__ ln_g, const float* __restrict__ ln_b) {
    __shared__ float shst[4][2][2];
    __shared__ float shab[4][2];
    int tid = threadIdx.x;
    int rg = tid >> 6, lt = tid & 63, wip = (tid >> 5) & 1, lane = tid & 31;
    int m = blockIdx.x * 4 + rg;
    int b = m >> 11, t = m & (TQ - 1);
    int h = lt >> 2, s0 = (lt & 3) * 16;
    int d0 = lt * 16;

    float val[16];
    const float* yp = g_y + ((size_t)(b * HQ + h) * TQ + t) * SQ + s0;
    float gs = 0.f, gq = 0.f;
    #pragma unroll
    for (int j = 0; j < 4; j++) {
        float4 a = *(const float4*)(yp + j * 4);
        val[j*4+0] = a.x; val[j*4+1] = a.y; val[j*4+2] = a.z; val[j*4+3] = a.w;
        gs += a.x + a.y + a.z + a.w;
        gq += a.x*a.x + a.y*a.y + a.z*a.z + a.w*a.w;
    }
    gs += __shfl_xor_sync(0xffffffffu, gs, 1); gq += __shfl_xor_sync(0xffffffffu, gq, 1);
    gs += __shfl_xor_sync(0xffffffffu, gs, 2); gq += __shfl_xor_sync(0xffffffffu, gq, 2);
    float gm = gs * (1.f / 64.f);
    float gvar = fmaxf(gq * (1.f / 64.f) - gm * gm, 0.f);
    float rstd = rsqrtf(gvar + 1e-5f);

    const float* gp = g_gate + (size_t)m * DQ + d0;
    float ssum = 0.f, ssq = 0.f;
    #pragma unroll
    for (int j = 0; j < 4; j++) {
        float4 gg = *(const float4*)(gp + j * 4);
        float4 gn4 = *(const float4*)(gn_g + d0 + j * 4);
        float4 gb4 = *(const float4*)(gn_b + d0 + j * 4);
        float gvv[4] = {gg.x, gg.y, gg.z, gg.w};
        float ga[4] = {gn4.x, gn4.y, gn4.z, gn4.w};
        float gbv[4] = {gb4.x, gb4.y, gb4.z, gb4.w};
        #pragma unroll
        for (int q = 0; q < 4; q++) {
            float yn = (val[j*4+q] - gm) * rstd * ga[q] + gbv[q];
            float v = yn * (gvv[q] / (1.f + expf(-gvv[q])));
            val[j*4+q] = v; ssum += v; ssq += v * v;
        }
    }
    ssum = warpsum(ssum); ssq = warpsum(ssq);
    if (lane == 0) { shst[rg][wip][0] = ssum; shst[rg][wip][1] = ssq; }
    __syncthreads();
    float ts  = shst[rg][0][0] + shst[rg][1][0];
    float ts2 = shst[rg][0][1] + shst[rg][1][1];
    float mean = ts * (1.f / DQ);
    float var = fmaxf(ts2 * (1.f / DQ) - mean * mean, 0.f);
    float lrstd = rsqrtf(var + 1e-5f);
    const float* lgp = ln_g + 4 * DQ + d0;
    const float* lbp = ln_b + 4 * DQ + d0;
    float sa = 0.f;
    #pragma unroll
    for (int j = 0; j < 4; j++) {
        float4 lg = *(const float4*)(lgp + j * 4);
        float4 lb = *(const float4*)(lbp + j * 4);
        float v0 = (val[j*4+0] - mean) * lrstd * lg.x + lb.x;
        float v1 = (val[j*4+1] - mean) * lrstd * lg.y + lb.y;
        float v2 = (val[j*4+2] - mean) * lrstd * lg.z + lb.z;
        float v3 = (val[j*4+3] - mean) * lrstd * lg.w + lb.w;
        val[j*4+0] = v0; val[j*4+1] = v1; val[j*4+2] = v2; val[j*4+3] = v3;
        sa += fabsf(v0) + fabsf(v1) + fabsf(v2) + fabsf(v3);
    }
    sa = warpsum(sa);
    if (lane == 0) shab[rg][wip] = sa;
    __syncthreads();
    float ma = (shab[rg][0] + shab[rg][1]) * (1.f / DQ);
    float scale = fmaxf(ma, 1e-8f) * 2.5f / 127.f;
    float inv = 1.f / scale;
    size_t off = (size_t)m * DQ + d0;
    #pragma unroll
    for (int g = 0; g < 2; g++) {
        uint4 u;
        float q0 = rintf(fminf(fmaxf(val[g*8+0] * inv, -127.f), 127.f));
        float q1 = rintf(fminf(fmaxf(val[g*8+1] * inv, -127.f), 127.f));
        float q2 = rintf(fminf(fmaxf(val[g*8+2] * inv, -127.f), 127.f));
        float q3 = rintf(fminf(fmaxf(val[g*8+3] * inv, -127.f), 127.f));
        float q4 = rintf(fminf(fmaxf(val[g*8+4] * inv, -127.f), 127.f));
        float q5 = rintf(fminf(fmaxf(val[g*8+5] * inv, -127.f), 127.f));
        float q6 = rintf(fminf(fmaxf(val[g*8+6] * inv, -127.f), 127.f));
        float q7 = rintf(fminf(fmaxf(val[g*8+7] * inv, -127.f), 127.f));
        u.x = bf2bits(q0, q1); u.y = bf2bits(q2, q3);
        u.z = bf2bits(q4, q5); u.w = bf2bits(q6, q7);
        *(uint4*)(g_xq5 + off + g * 8) = u;
    }
    if (lt == 0) g_xscale5[m] = scale;
}

// ---------------- launcher ----------------------------------------------------
#define GEMM_SMEM (3 * STAGE_BYTES + 1024)
#define WKV_SMEM  (2 * WKV_BUF * 4)

extern "C" void kernel_launch(void* const* d_in, const int* in_sizes, int n_in,
                              void* d_out, int out_size) {
    const float* x         = (const float*)d_in[0];
    const float* mu_r      = (const float*)d_in[1];
    const float* mu_k      = (const float*)d_in[2];
    const float* mu_v      = (const float*)d_in[3];
    const float* mu_g      = (const float*)d_in[4];
    const float* log_decay = (const float*)d_in[5];
    const float* u         = (const float*)d_in[6];
    const float* proj_w    = (const float*)d_in[7];
    const float* ln_g      = (const float*)d_in[8];
    const float* ln_b      = (const float*)d_in[9];
    const float* gn_g      = (const float*)d_in[10];
    const float* gn_b      = (const float*)d_in[11];
    float* out = (float*)d_out;

    cudaFuncSetAttribute(gemm_mma_kernel, cudaFuncAttributeMaxDynamicSharedMemorySize, GEMM_SMEM);
    cudaFuncSetAttribute(wkv_kernel, cudaFuncAttributeMaxDynamicSharedMemorySize, WKV_SMEM);

    // wkv is launch #4 -> lands in the ncu capture slot
    wq_scale_kernel<<<dim3(64, 5), 256>>>(proj_w);
    quant_lnq4_kernel<<<5120 + 2048, 256>>>(proj_w, x, mu_r, mu_k, mu_v, mu_g, ln_g, ln_b);
    gemm_mma_kernel<<<dim3(64, 8, 4), 256, GEMM_SMEM>>>(nullptr);
    wkv_kernel<<<128, 128, WKV_SMEM>>>(log_decay, u);
    gngate_kernel<<<2048, 256>>>(gn_g, gn_b, ln_g, ln_b);
    gemm_mma_kernel<<<dim3(64, 8, 1), 256, GEMM_SMEM>>>(out);
}